// round 1
// baseline (speedup 1.0000x reference)
#include <cuda_runtime.h>

#define BB 2
#define CC 128
#define NH 32
#define SP 16384   // T*H*W
#define NN 1024
#define TBL 6727   // (2T-1)*(2h-1)*(2w-1) = 7*31*31
#define EPS 1e-5f

// ---- scratch (device globals; no allocation allowed) ----
__device__ float g_raw[3][BB][CC][SP];     // projected q/k/v pre-norm  (~50MB)
__device__ float g_mu[3][BB][NH];
__device__ float g_rs[3][BB][NH];
__device__ float g_qp[BB][NH][NN][4];      // pooled normalized queries
__device__ float g_kp[BB][NH][NN][4];      // pooled normalized keys
__device__ float g_vp[BB][NH][NN][64];     // full-res normalized values (d*16+p)

// ============================================================
// K1: pointwise projections  out[z][b][o][s] = sum_c W[o,c]*x[b,c,s]
// tile: 128 o x 64 s, K-chunks of 16.  grid (256, 2, 3)
// ============================================================
__global__ __launch_bounds__(256) void proj_kernel(
    const float* __restrict__ x,
    const float* __restrict__ Wq, const float* __restrict__ Wk,
    const float* __restrict__ Wv) {
  const int z = blockIdx.z, b = blockIdx.y;
  const int s0 = blockIdx.x * 64;
  const float* __restrict__ Wm = (z == 0) ? Wq : (z == 1 ? Wk : Wv);
  __shared__ float Ws[16][128];
  __shared__ float xs[16][64];
  const int t = threadIdx.x, tx = t & 15, ty = t >> 4;
  float acc[8][4];
#pragma unroll
  for (int i = 0; i < 8; i++) { acc[i][0]=0.f; acc[i][1]=0.f; acc[i][2]=0.f; acc[i][3]=0.f; }
  const float* xb = x + (size_t)b * CC * SP;
  for (int kc = 0; kc < 128; kc += 16) {
    {
      int o = t >> 1, koff = (t & 1) * 8;
      const float* wp = Wm + o * 128 + kc + koff;
      float4 w0 = *(const float4*)wp;
      float4 w1 = *(const float4*)(wp + 4);
      Ws[koff + 0][o] = w0.x; Ws[koff + 1][o] = w0.y;
      Ws[koff + 2][o] = w0.z; Ws[koff + 3][o] = w0.w;
      Ws[koff + 4][o] = w1.x; Ws[koff + 5][o] = w1.y;
      Ws[koff + 6][o] = w1.z; Ws[koff + 7][o] = w1.w;
    }
    *(float4*)&xs[ty][tx * 4] = *(const float4*)&xb[(size_t)(kc + ty) * SP + s0 + tx * 4];
    __syncthreads();
#pragma unroll
    for (int k = 0; k < 16; k++) {
      float4 a0 = *(float4*)&Ws[k][ty * 8];
      float4 a1 = *(float4*)&Ws[k][ty * 8 + 4];
      float4 bv = *(float4*)&xs[k][tx * 4];
      float av[8] = {a0.x, a0.y, a0.z, a0.w, a1.x, a1.y, a1.z, a1.w};
      float bw[4] = {bv.x, bv.y, bv.z, bv.w};
#pragma unroll
      for (int i = 0; i < 8; i++)
#pragma unroll
        for (int j = 0; j < 4; j++)
          acc[i][j] = fmaf(av[i], bw[j], acc[i][j]);
    }
    __syncthreads();
  }
  float* outb = &g_raw[z][b][0][0];
#pragma unroll
  for (int i = 0; i < 8; i++) {
    int o = ty * 8 + i;
    *(float4*)&outb[(size_t)o * SP + s0 + tx * 4] =
        make_float4(acc[i][0], acc[i][1], acc[i][2], acc[i][3]);
  }
}

// ============================================================
// K2: GroupNorm stats per (z,b,g): mean/var over 4 ch * 16384
// grid 192 blocks
// ============================================================
__global__ __launch_bounds__(256) void gn_stats_kernel() {
  int idx = blockIdx.x;
  int g = idx & 31, b = (idx >> 5) & 1, z = idx >> 6;
  const float* base = &g_raw[z][b][g * 4][0];
  float s = 0.f, s2 = 0.f;
  for (int i = threadIdx.x; i < 65536; i += 256) {
    float v = base[i];
    s += v; s2 = fmaf(v, v, s2);
  }
  __shared__ float sh1[256], sh2[256];
  sh1[threadIdx.x] = s; sh2[threadIdx.x] = s2;
  __syncthreads();
  for (int str = 128; str > 0; str >>= 1) {
    if (threadIdx.x < str) {
      sh1[threadIdx.x] += sh1[threadIdx.x + str];
      sh2[threadIdx.x] += sh2[threadIdx.x + str];
    }
    __syncthreads();
  }
  if (threadIdx.x == 0) {
    float mu = sh1[0] * (1.f / 65536.f);
    float var = sh2[0] * (1.f / 65536.f) - mu * mu;
    g_mu[z][b][g] = mu;
    g_rs[z][b][g] = rsqrtf(var + EPS);
  }
}

// ============================================================
// K3: normalize + patchify + pool.  4 tokens per 256-thread block.
// token = (b,g,n); lane e = d*16+p.
// ============================================================
__global__ __launch_bounds__(256) void rearrange_kernel(
    const float* __restrict__ gqg, const float* __restrict__ gqb,
    const float* __restrict__ gkg, const float* __restrict__ gkb,
    const float* __restrict__ gvg, const float* __restrict__ gvb) {
  int tok = blockIdx.x * 4 + (threadIdx.x >> 6);
  int e = threadIdx.x & 63;
  int n = tok & 1023, g = (tok >> 10) & 31, b = tok >> 15;
  int d = e >> 4, p = e & 15;
  int c = g * 4 + d;
  int tt = n >> 8, hy = (n >> 4) & 15, wx = n & 15, sy = p >> 2, sx = p & 3;
  int pix = (tt * 64 + hy * 4 + sy) * 64 + wx * 4 + sx;
#pragma unroll
  for (int z = 0; z < 3; z++) {
    const float* ga = (z == 0) ? gqg : ((z == 1) ? gkg : gvg);
    const float* be = (z == 0) ? gqb : ((z == 1) ? gkb : gvb);
    float mu = g_mu[z][b][g], rs = g_rs[z][b][g];
    float v = (g_raw[z][b][c][pix] - mu) * rs * ga[c] + be[c];
    if (z == 2) {
      g_vp[b][g][n][e] = v;
    } else {
      float r = v;
      r += __shfl_xor_sync(0xffffffffu, r, 8);
      r += __shfl_xor_sync(0xffffffffu, r, 4);
      r += __shfl_xor_sync(0xffffffffu, r, 2);
      r += __shfl_xor_sync(0xffffffffu, r, 1);
      if (p == 0) {
        if (z == 0) g_qp[b][g][n][d] = r * (1.f / 16.f);
        else        g_kp[b][g][n][d] = r * (1.f / 16.f);
      }
    }
  }
}

// ============================================================
// K4: fused attention.  One block = (b,g, 64-row tile).
// Online softmax over 8 chunks of 128 keys.  rel_table[g] in smem.
// grid (16, 32, 2), 256 threads, ~96.5KB dynamic smem.
// ============================================================
__global__ __launch_bounds__(256) void attn_kernel(
    const float* __restrict__ rel_table, const int* __restrict__ rel_index,
    float* __restrict__ out) {
  extern __shared__ float sm[];
  float* tab = sm;                 // 6728
  float* qs  = tab + 6728;         // 256   [r*4+d]
  float* ks  = qs + 256;           // 512   [m*4+d]
  float* vs  = ks + 512;           // 8192  [m*64+j]
  float* Pb  = vs + 8192;          // 64*129 [r*129+m]
  float* Mr  = Pb + 64 * 129;      // 64
  float* Sr  = Mr + 64;            // 64
  float* Fr  = Sr + 64;            // 64

  const int tile = blockIdx.x, g = blockIdx.y, b = blockIdx.z;
  const int n0 = tile * 64;
  const int t = threadIdx.x, tx = t & 15, ty = t >> 4;

  for (int i = t; i < TBL; i += 256) tab[i] = rel_table[g * TBL + i];
  qs[t] = g_qp[b][g][n0 + (t >> 2)][t & 3];
  if (t < 64) { Mr[t] = -3e38f; Sr[t] = 0.f; }
  float acc[4][4];
#pragma unroll
  for (int i = 0; i < 4; i++) { acc[i][0]=0.f; acc[i][1]=0.f; acc[i][2]=0.f; acc[i][3]=0.f; }
  __syncthreads();

  for (int ch = 0; ch < 8; ch++) {
    const int m0 = ch * 128;
    const float* kpb = &g_kp[b][g][m0][0];
    ks[t] = kpb[t];
    ks[t + 256] = kpb[t + 256];
    const float4* vpb = (const float4*)&g_vp[b][g][m0][0];
#pragma unroll
    for (int i = 0; i < 8; i++) {
      int li = t + i * 256;
      ((float4*)vs)[li] = vpb[li];
    }
    __syncthreads();

    // logits = 0.5*q.k + rel_table[rel_index]
#pragma unroll 4
    for (int it = 0; it < 32; it++) {
      int idx = t + it * 256;
      int r = idx >> 7, m = idx & 127;
      float4 qv = *(float4*)&qs[r * 4];
      float4 kv = *(float4*)&ks[m * 4];
      float l = (qv.x * kv.x + qv.y * kv.y + qv.z * kv.z + qv.w * kv.w) * 0.5f;
      l += tab[rel_index[(size_t)(n0 + r) * 1024 + m0 + m]];
      Pb[r * 129 + m] = l;
    }
    __syncthreads();

    // online softmax: 4 threads per row (same warp)
    {
      int r = t >> 2, j = t & 3;
      float* prow = Pb + r * 129 + j;
      float mx = -3e38f;
#pragma unroll
      for (int k = 0; k < 32; k++) mx = fmaxf(mx, prow[4 * k]);
      mx = fmaxf(mx, __shfl_xor_sync(0xffffffffu, mx, 1));
      mx = fmaxf(mx, __shfl_xor_sync(0xffffffffu, mx, 2));
      float Mold = Mr[r];
      float Mn = fmaxf(Mold, mx);
      float ssum = 0.f;
#pragma unroll
      for (int k = 0; k < 32; k++) {
        float e = __expf(prow[4 * k] - Mn);
        prow[4 * k] = e;
        ssum += e;
      }
      ssum += __shfl_xor_sync(0xffffffffu, ssum, 1);
      ssum += __shfl_xor_sync(0xffffffffu, ssum, 2);
      if (j == 0) {
        float f = __expf(Mold - Mn);
        Sr[r] = Sr[r] * f + ssum;
        Mr[r] = Mn;
        Fr[r] = f;
      }
    }
    __syncthreads();

    // rescale accumulator + PV
#pragma unroll
    for (int i = 0; i < 4; i++) {
      float f = Fr[ty * 4 + i];
      acc[i][0] *= f; acc[i][1] *= f; acc[i][2] *= f; acc[i][3] *= f;
    }
#pragma unroll 2
    for (int m = 0; m < 128; m++) {
      float4 vv = *(float4*)&vs[m * 64 + tx * 4];
      float p0 = Pb[(ty * 4 + 0) * 129 + m];
      float p1 = Pb[(ty * 4 + 1) * 129 + m];
      float p2 = Pb[(ty * 4 + 2) * 129 + m];
      float p3 = Pb[(ty * 4 + 3) * 129 + m];
      acc[0][0] = fmaf(p0, vv.x, acc[0][0]); acc[0][1] = fmaf(p0, vv.y, acc[0][1]);
      acc[0][2] = fmaf(p0, vv.z, acc[0][2]); acc[0][3] = fmaf(p0, vv.w, acc[0][3]);
      acc[1][0] = fmaf(p1, vv.x, acc[1][0]); acc[1][1] = fmaf(p1, vv.y, acc[1][1]);
      acc[1][2] = fmaf(p1, vv.z, acc[1][2]); acc[1][3] = fmaf(p1, vv.w, acc[1][3]);
      acc[2][0] = fmaf(p2, vv.x, acc[2][0]); acc[2][1] = fmaf(p2, vv.y, acc[2][1]);
      acc[2][2] = fmaf(p2, vv.z, acc[2][2]); acc[2][3] = fmaf(p2, vv.w, acc[2][3]);
      acc[3][0] = fmaf(p3, vv.x, acc[3][0]); acc[3][1] = fmaf(p3, vv.y, acc[3][1]);
      acc[3][2] = fmaf(p3, vv.z, acc[3][2]); acc[3][3] = fmaf(p3, vv.w, acc[3][3]);
    }
    __syncthreads();
  }

  // epilogue: divide by row sum, scatter to (b,c,t,H,W)
  int d = tx >> 2, sy = tx & 3;
#pragma unroll
  for (int i = 0; i < 4; i++) {
    int n = n0 + ty * 4 + i;
    int tt = n >> 8, hy = (n >> 4) & 15, wx = n & 15;
    float inv = 1.f / Sr[ty * 4 + i];
    size_t off = ((((size_t)b * 128 + g * 4 + d) * 4 + tt) * 64 + hy * 4 + sy) * 64 + wx * 4;
    *(float4*)&out[off] =
        make_float4(acc[i][0] * inv, acc[i][1] * inv, acc[i][2] * inv, acc[i][3] * inv);
  }
}

// ============================================================
extern "C" void kernel_launch(void* const* d_in, const int* in_sizes, int n_in,
                              void* d_out, int out_size) {
  (void)in_sizes; (void)n_in; (void)out_size;
  const float* x   = (const float*)d_in[0];
  const float* Wq  = (const float*)d_in[1];
  const float* Wk  = (const float*)d_in[2];
  const float* Wv  = (const float*)d_in[3];
  const float* gqg = (const float*)d_in[4];
  const float* gqb = (const float*)d_in[5];
  const float* gkg = (const float*)d_in[6];
  const float* gkb = (const float*)d_in[7];
  const float* gvg = (const float*)d_in[8];
  const float* gvb = (const float*)d_in[9];
  const float* rel_table = (const float*)d_in[10];
  const int*   rel_index = (const int*)d_in[11];
  float* out = (float*)d_out;

  cudaFuncSetAttribute(attn_kernel, cudaFuncAttributeMaxDynamicSharedMemorySize, 96544);

  proj_kernel<<<dim3(256, 2, 3), 256>>>(x, Wq, Wk, Wv);
  gn_stats_kernel<<<192, 256>>>();
  rearrange_kernel<<<16384, 256>>>(gqg, gqb, gkg, gkb, gvg, gvb);
  attn_kernel<<<dim3(16, 32, 2), 256, 96544>>>(rel_table, rel_index, out);
}

// round 2
// speedup vs baseline: 1.3960x; 1.3960x over previous
#include <cuda_runtime.h>

#define BB 2
#define CC 128
#define NH 32
#define SP 16384   // T*H*W
#define NN 1024
#define TBL 6727   // (2T-1)*(2h-1)*(2w-1) = 7*31*31
#define EPS 1e-5f

// ---- scratch (device globals; no allocation allowed) ----
__device__ float g_raw[3][BB][CC][SP];     // projected q/k/v pre-norm  (~50MB)
__device__ float g_mu[3][BB][NH];
__device__ float g_rs[3][BB][NH];
__device__ float g_qp[BB][NH][NN][4];      // pooled normalized queries
__device__ float g_kp[BB][NH][NN][4];      // pooled normalized keys
__device__ float g_vp[BB][NH][NN][64];     // full-res normalized values (d*16+p)

__device__ __forceinline__ void ffma2(unsigned long long& d, unsigned long long a,
                                      unsigned long long b) {
  asm("fma.rn.f32x2 %0, %1, %2, %0;" : "+l"(d) : "l"(a), "l"(b));
}
__device__ __forceinline__ unsigned long long pack2(float lo, float hi) {
  unsigned long long r;
  asm("mov.b64 %0, {%1, %2};" : "=l"(r) : "f"(lo), "f"(hi));
  return r;
}
__device__ __forceinline__ void unpack2(unsigned long long v, float& lo, float& hi) {
  asm("mov.b64 {%0, %1}, %2;" : "=f"(lo), "=f"(hi) : "l"(v));
}

// ============================================================
// K1: pointwise projections  out[z][b][o][s] = sum_c W[o,c]*x[b,c,s]
// ============================================================
__global__ __launch_bounds__(256) void proj_kernel(
    const float* __restrict__ x,
    const float* __restrict__ Wq, const float* __restrict__ Wk,
    const float* __restrict__ Wv) {
  const int z = blockIdx.z, b = blockIdx.y;
  const int s0 = blockIdx.x * 64;
  const float* __restrict__ Wm = (z == 0) ? Wq : (z == 1 ? Wk : Wv);
  __shared__ float Ws[16][128];
  __shared__ float xs[16][64];
  const int t = threadIdx.x, tx = t & 15, ty = t >> 4;
  float acc[8][4];
#pragma unroll
  for (int i = 0; i < 8; i++) { acc[i][0]=0.f; acc[i][1]=0.f; acc[i][2]=0.f; acc[i][3]=0.f; }
  const float* xb = x + (size_t)b * CC * SP;
  for (int kc = 0; kc < 128; kc += 16) {
    {
      int o = t >> 1, koff = (t & 1) * 8;
      const float* wp = Wm + o * 128 + kc + koff;
      float4 w0 = *(const float4*)wp;
      float4 w1 = *(const float4*)(wp + 4);
      Ws[koff + 0][o] = w0.x; Ws[koff + 1][o] = w0.y;
      Ws[koff + 2][o] = w0.z; Ws[koff + 3][o] = w0.w;
      Ws[koff + 4][o] = w1.x; Ws[koff + 5][o] = w1.y;
      Ws[koff + 6][o] = w1.z; Ws[koff + 7][o] = w1.w;
    }
    *(float4*)&xs[ty][tx * 4] = *(const float4*)&xb[(size_t)(kc + ty) * SP + s0 + tx * 4];
    __syncthreads();
#pragma unroll
    for (int k = 0; k < 16; k++) {
      float4 a0 = *(float4*)&Ws[k][ty * 8];
      float4 a1 = *(float4*)&Ws[k][ty * 8 + 4];
      float4 bv = *(float4*)&xs[k][tx * 4];
      float av[8] = {a0.x, a0.y, a0.z, a0.w, a1.x, a1.y, a1.z, a1.w};
      float bw[4] = {bv.x, bv.y, bv.z, bv.w};
#pragma unroll
      for (int i = 0; i < 8; i++)
#pragma unroll
        for (int j = 0; j < 4; j++)
          acc[i][j] = fmaf(av[i], bw[j], acc[i][j]);
    }
    __syncthreads();
  }
  float* outb = &g_raw[z][b][0][0];
#pragma unroll
  for (int i = 0; i < 8; i++) {
    int o = ty * 8 + i;
    *(float4*)&outb[(size_t)o * SP + s0 + tx * 4] =
        make_float4(acc[i][0], acc[i][1], acc[i][2], acc[i][3]);
  }
}

// ============================================================
// K2: GroupNorm stats per (z,b,g)
// ============================================================
__global__ __launch_bounds__(256) void gn_stats_kernel() {
  int idx = blockIdx.x;
  int g = idx & 31, b = (idx >> 5) & 1, z = idx >> 6;
  const float* base = &g_raw[z][b][g * 4][0];
  float s = 0.f, s2 = 0.f;
  for (int i = threadIdx.x; i < 65536; i += 256) {
    float v = base[i];
    s += v; s2 = fmaf(v, v, s2);
  }
  __shared__ float sh1[256], sh2[256];
  sh1[threadIdx.x] = s; sh2[threadIdx.x] = s2;
  __syncthreads();
  for (int str = 128; str > 0; str >>= 1) {
    if (threadIdx.x < str) {
      sh1[threadIdx.x] += sh1[threadIdx.x + str];
      sh2[threadIdx.x] += sh2[threadIdx.x + str];
    }
    __syncthreads();
  }
  if (threadIdx.x == 0) {
    float mu = sh1[0] * (1.f / 65536.f);
    float var = sh2[0] * (1.f / 65536.f) - mu * mu;
    g_mu[z][b][g] = mu;
    g_rs[z][b][g] = rsqrtf(var + EPS);
  }
}

// ============================================================
// K3: normalize + patchify + pool
// ============================================================
__global__ __launch_bounds__(256) void rearrange_kernel(
    const float* __restrict__ gqg, const float* __restrict__ gqb,
    const float* __restrict__ gkg, const float* __restrict__ gkb,
    const float* __restrict__ gvg, const float* __restrict__ gvb) {
  int tok = blockIdx.x * 4 + (threadIdx.x >> 6);
  int e = threadIdx.x & 63;
  int n = tok & 1023, g = (tok >> 10) & 31, b = tok >> 15;
  int d = e >> 4, p = e & 15;
  int c = g * 4 + d;
  int tt = n >> 8, hy = (n >> 4) & 15, wx = n & 15, sy = p >> 2, sx = p & 3;
  int pix = (tt * 64 + hy * 4 + sy) * 64 + wx * 4 + sx;
#pragma unroll
  for (int z = 0; z < 3; z++) {
    const float* ga = (z == 0) ? gqg : ((z == 1) ? gkg : gvg);
    const float* be = (z == 0) ? gqb : ((z == 1) ? gkb : gvb);
    float mu = g_mu[z][b][g], rs = g_rs[z][b][g];
    float v = (g_raw[z][b][c][pix] - mu) * rs * ga[c] + be[c];
    if (z == 2) {
      g_vp[b][g][n][e] = v;
    } else {
      float r = v;
      r += __shfl_xor_sync(0xffffffffu, r, 8);
      r += __shfl_xor_sync(0xffffffffu, r, 4);
      r += __shfl_xor_sync(0xffffffffu, r, 2);
      r += __shfl_xor_sync(0xffffffffu, r, 1);
      if (p == 0) {
        if (z == 0) g_qp[b][g][n][d] = r * (1.f / 16.f);
        else        g_kp[b][g][n][d] = r * (1.f / 16.f);
      }
    }
  }
}

// ============================================================
// K4: fused attention v2.
//  - One block = (b,g, 64-row tile); 8 chunks of 128 keys.
//  - Logits + exp fully in registers (warp owns 8 rows; lane owns 4
//    contiguous m), K chunk register-resident, single conflict-free
//    STS.128 of P per (row,lane). No max-subtraction (values bounded
//    by GroupNorm; exp stays deep inside fp32 range), row-sum kept in
//    registers, warp-reduced once at the end.
//  - PV: 4-m unrolled, vectorized LDS.128 for P and V, f32x2 packed FMA.
//  grid (16, 32, 2), 256 threads, 94.5KB smem -> 2 blocks/SM.
// ============================================================
__global__ __launch_bounds__(256, 2) void attn_kernel(
    const float* __restrict__ rel_table, const int* __restrict__ rel_index,
    float* __restrict__ out) {
  extern __shared__ float sm[];
  float* tab = sm;                 // 6728
  float* qs  = tab + 6728;         // 256   [r*4+d]
  float* vs  = qs + 256;           // 8192  [m*64+e]
  float* Pb  = vs + 8192;          // 64*132 row-major [r][m], stride 132

  const int tile = blockIdx.x, g = blockIdx.y, b = blockIdx.z;
  const int n0 = tile * 64;
  const int t = threadIdx.x;
  const int lane = t & 31, w = t >> 5;
  const int tx = t & 15, ty = t >> 4;
  const int tyloc = (t >> 4) & 1;

  for (int i = t; i < TBL; i += 256) tab[i] = rel_table[g * TBL + i];
  qs[t] = g_qp[b][g][n0 + (t >> 2)][t & 3];

  unsigned long long acc[4][2];
#pragma unroll
  for (int i = 0; i < 4; i++) { acc[i][0] = 0ull; acc[i][1] = 0ull; }
  float srow[8];
#pragma unroll
  for (int k = 0; k < 8; k++) srow[k] = 0.f;

  __syncthreads();

  for (int ch = 0; ch < 8; ch++) {
    const int m0 = ch * 128;
    if (ch) __syncthreads();  // previous PV done before vs/Pb overwrite

    // stage V chunk (128 x 64 floats)
    const float4* vsrc = (const float4*)&g_vp[b][g][m0][0];
#pragma unroll
    for (int i = 0; i < 8; i++)
      ((float4*)vs)[t + i * 256] = vsrc[t + i * 256];

    // K chunk for this lane's 4 m-values, register resident
    float4 kreg[4];
#pragma unroll
    for (int j = 0; j < 4; j++)
      kreg[j] = *(const float4*)&g_kp[b][g][m0 + lane * 4 + j][0];

    // logits + exp for this warp's 8 rows
    const int rbase = w * 8;
#pragma unroll
    for (int k = 0; k < 8; k++) {
      const int r = rbase + k;
      float4 qv = *(float4*)&qs[r * 4];
      int4 idx = *(const int4*)&rel_index[(size_t)(n0 + r) * 1024 + m0 + lane * 4];
      float l0 = 0.5f * (qv.x*kreg[0].x + qv.y*kreg[0].y + qv.z*kreg[0].z + qv.w*kreg[0].w) + tab[idx.x];
      float l1 = 0.5f * (qv.x*kreg[1].x + qv.y*kreg[1].y + qv.z*kreg[1].z + qv.w*kreg[1].w) + tab[idx.y];
      float l2 = 0.5f * (qv.x*kreg[2].x + qv.y*kreg[2].y + qv.z*kreg[2].z + qv.w*kreg[2].w) + tab[idx.z];
      float l3 = 0.5f * (qv.x*kreg[3].x + qv.y*kreg[3].y + qv.z*kreg[3].z + qv.w*kreg[3].w) + tab[idx.w];
      float e0 = __expf(l0), e1 = __expf(l1), e2 = __expf(l2), e3 = __expf(l3);
      srow[k] += (e0 + e1) + (e2 + e3);
      *(float4*)&Pb[r * 132 + lane * 4] = make_float4(e0, e1, e2, e3);
    }
    __syncthreads();

    // PV: acc[r][c] += P[r][m] * V[m][c], 4 m per iteration
#pragma unroll 2
    for (int mi = 0; mi < 32; mi++) {
      const int m = mi * 4;
      float4 pr[4];
#pragma unroll
      for (int i = 0; i < 4; i++)
        pr[i] = *(float4*)&Pb[(ty * 4 + i) * 132 + m];
#pragma unroll
      for (int j = 0; j < 4; j++) {
        float4 vv = *(float4*)&vs[(m + j) * 64 + tx * 4];
        unsigned long long v01 = pack2(vv.x, vv.y);
        unsigned long long v23 = pack2(vv.z, vv.w);
#pragma unroll
        for (int i = 0; i < 4; i++) {
          float p = (j == 0) ? pr[i].x : (j == 1) ? pr[i].y : (j == 2) ? pr[i].z : pr[i].w;
          unsigned long long pd = pack2(p, p);
          ffma2(acc[i][0], pd, v01);
          ffma2(acc[i][1], pd, v23);
        }
      }
    }
  }

  // reduce row sums across each warp (all lanes end with full row sums)
#pragma unroll
  for (int k = 0; k < 8; k++) {
    float s = srow[k];
    s += __shfl_xor_sync(0xffffffffu, s, 16);
    s += __shfl_xor_sync(0xffffffffu, s, 8);
    s += __shfl_xor_sync(0xffffffffu, s, 4);
    s += __shfl_xor_sync(0xffffffffu, s, 2);
    s += __shfl_xor_sync(0xffffffffu, s, 1);
    srow[k] = s;
  }

  // epilogue: scale by 1/S and scatter to (b,c,t,H,W)
  const int d = tx >> 2, sy = tx & 3;
#pragma unroll
  for (int i = 0; i < 4; i++) {
    float S = tyloc ? srow[4 + i] : srow[i];
    float inv = 1.f / S;
    float a0, a1, a2, a3;
    unpack2(acc[i][0], a0, a1);
    unpack2(acc[i][1], a2, a3);
    int n = n0 + ty * 4 + i;
    int tt = n >> 8, hy = (n >> 4) & 15, wx = n & 15;
    size_t off = ((((size_t)b * 128 + g * 4 + d) * 4 + tt) * 64 + hy * 4 + sy) * 64 + wx * 4;
    *(float4*)&out[off] = make_float4(a0 * inv, a1 * inv, a2 * inv, a3 * inv);
  }
}

// ============================================================
extern "C" void kernel_launch(void* const* d_in, const int* in_sizes, int n_in,
                              void* d_out, int out_size) {
  (void)in_sizes; (void)n_in; (void)out_size;
  const float* x   = (const float*)d_in[0];
  const float* Wq  = (const float*)d_in[1];
  const float* Wk  = (const float*)d_in[2];
  const float* Wv  = (const float*)d_in[3];
  const float* gqg = (const float*)d_in[4];
  const float* gqb = (const float*)d_in[5];
  const float* gkg = (const float*)d_in[6];
  const float* gkb = (const float*)d_in[7];
  const float* gvg = (const float*)d_in[8];
  const float* gvb = (const float*)d_in[9];
  const float* rel_table = (const float*)d_in[10];
  const int*   rel_index = (const int*)d_in[11];
  float* out = (float*)d_out;

  const int smem = (6728 + 256 + 8192 + 64 * 132) * sizeof(float);  // 94496
  cudaFuncSetAttribute(attn_kernel, cudaFuncAttributeMaxDynamicSharedMemorySize, smem);

  proj_kernel<<<dim3(256, 2, 3), 256>>>(x, Wq, Wk, Wv);
  gn_stats_kernel<<<192, 256>>>();
  rearrange_kernel<<<16384, 256>>>(gqg, gqb, gkg, gkb, gvg, gvb);
  attn_kernel<<<dim3(16, 32, 2), 256, smem>>>(rel_table, rel_index, out);
}

// round 4
// speedup vs baseline: 1.4660x; 1.0501x over previous
#include <cuda_runtime.h>

#define BB 2
#define CC 128
#define NH 32
#define SP 16384   // T*H*W
#define NN 1024
#define TBL 6727   // (2T-1)*(2h-1)*(2w-1) = 7*31*31
#define EPS 1e-5f
#define PSTR 68    // Pt row stride (multiple of 4: float4-aligned; 68%32=4 -> conflict-free phases)

typedef unsigned long long ull;

// ---- scratch (device globals; no allocation allowed) ----
__device__ float g_raw[3][BB][CC][SP];     // projected q/k/v pre-norm  (~50MB)
__device__ float g_mu[3][BB][NH];
__device__ float g_rs[3][BB][NH];
__device__ float g_qp[BB][NH][NN][4];      // pooled normalized queries
__device__ float g_kp[BB][NH][NN][4];      // pooled normalized keys
__device__ float g_vp[BB][NH][NN][64];     // full-res normalized values (d*16+p)

__device__ __forceinline__ void ffma2(ull& d, ull a, ull b) {
  asm("fma.rn.f32x2 %0, %1, %2, %0;" : "+l"(d) : "l"(a), "l"(b));
}
__device__ __forceinline__ ull pack2(float lo, float hi) {
  ull r;
  asm("mov.b64 %0, {%1, %2};" : "=l"(r) : "f"(lo), "f"(hi));
  return r;
}
__device__ __forceinline__ void unpack2(ull v, float& lo, float& hi) {
  asm("mov.b64 {%0, %1}, %2;" : "=f"(lo), "=f"(hi) : "l"(v));
}

// ============================================================
// K1: pointwise projections  out[z][b][o][s] = sum_c W[o,c]*x[b,c,s]
// f32x2 packed accumulators: 16 FFMA2 per k-step per thread.
// ============================================================
__global__ __launch_bounds__(256) void proj_kernel(
    const float* __restrict__ x,
    const float* __restrict__ Wq, const float* __restrict__ Wk,
    const float* __restrict__ Wv) {
  const int z = blockIdx.z, b = blockIdx.y;
  const int s0 = blockIdx.x * 64;
  const float* __restrict__ Wm = (z == 0) ? Wq : (z == 1 ? Wk : Wv);
  __shared__ float Ws[16][128];
  __shared__ float xs[16][64];
  const int t = threadIdx.x, tx = t & 15, ty = t >> 4;
  ull acc[8][2];
#pragma unroll
  for (int i = 0; i < 8; i++) { acc[i][0] = 0ull; acc[i][1] = 0ull; }
  const float* xb = x + (size_t)b * CC * SP;
  for (int kc = 0; kc < 128; kc += 16) {
    {
      int o = t >> 1, koff = (t & 1) * 8;
      const float* wp = Wm + o * 128 + kc + koff;
      float4 w0 = *(const float4*)wp;
      float4 w1 = *(const float4*)(wp + 4);
      Ws[koff + 0][o] = w0.x; Ws[koff + 1][o] = w0.y;
      Ws[koff + 2][o] = w0.z; Ws[koff + 3][o] = w0.w;
      Ws[koff + 4][o] = w1.x; Ws[koff + 5][o] = w1.y;
      Ws[koff + 6][o] = w1.z; Ws[koff + 7][o] = w1.w;
    }
    *(float4*)&xs[ty][tx * 4] = *(const float4*)&xb[(size_t)(kc + ty) * SP + s0 + tx * 4];
    __syncthreads();
#pragma unroll
    for (int k = 0; k < 16; k++) {
      float4 a0 = *(float4*)&Ws[k][ty * 8];
      float4 a1 = *(float4*)&Ws[k][ty * 8 + 4];
      float4 bv = *(float4*)&xs[k][tx * 4];
      ull b01 = pack2(bv.x, bv.y), b23 = pack2(bv.z, bv.w);
      float av[8] = {a0.x, a0.y, a0.z, a0.w, a1.x, a1.y, a1.z, a1.w};
#pragma unroll
      for (int i = 0; i < 8; i++) {
        ull ad = pack2(av[i], av[i]);
        ffma2(acc[i][0], ad, b01);
        ffma2(acc[i][1], ad, b23);
      }
    }
    __syncthreads();
  }
  float* outb = &g_raw[z][b][0][0];
#pragma unroll
  for (int i = 0; i < 8; i++) {
    int o = ty * 8 + i;
    float r0, r1, r2, r3;
    unpack2(acc[i][0], r0, r1);
    unpack2(acc[i][1], r2, r3);
    *(float4*)&outb[(size_t)o * SP + s0 + tx * 4] = make_float4(r0, r1, r2, r3);
  }
}

// ============================================================
// K2: GroupNorm stats per (z,b,g)
// ============================================================
__global__ __launch_bounds__(256) void gn_stats_kernel() {
  int idx = blockIdx.x;
  int g = idx & 31, b = (idx >> 5) & 1, z = idx >> 6;
  const float* base = &g_raw[z][b][g * 4][0];
  float s = 0.f, s2 = 0.f;
  for (int i = threadIdx.x; i < 65536; i += 256) {
    float v = base[i];
    s += v; s2 = fmaf(v, v, s2);
  }
  __shared__ float sh1[256], sh2[256];
  sh1[threadIdx.x] = s; sh2[threadIdx.x] = s2;
  __syncthreads();
  for (int str = 128; str > 0; str >>= 1) {
    if (threadIdx.x < str) {
      sh1[threadIdx.x] += sh1[threadIdx.x + str];
      sh2[threadIdx.x] += sh2[threadIdx.x + str];
    }
    __syncthreads();
  }
  if (threadIdx.x == 0) {
    float mu = sh1[0] * (1.f / 65536.f);
    float var = sh2[0] * (1.f / 65536.f) - mu * mu;
    g_mu[z][b][g] = mu;
    g_rs[z][b][g] = rsqrtf(var + EPS);
  }
}

// ============================================================
// K3: normalize + patchify + pool
// ============================================================
__global__ __launch_bounds__(256) void rearrange_kernel(
    const float* __restrict__ gqg, const float* __restrict__ gqb,
    const float* __restrict__ gkg, const float* __restrict__ gkb,
    const float* __restrict__ gvg, const float* __restrict__ gvb) {
  int tok = blockIdx.x * 4 + (threadIdx.x >> 6);
  int e = threadIdx.x & 63;
  int n = tok & 1023, g = (tok >> 10) & 31, b = tok >> 15;
  int d = e >> 4, p = e & 15;
  int c = g * 4 + d;
  int tt = n >> 8, hy = (n >> 4) & 15, wx = n & 15, sy = p >> 2, sx = p & 3;
  int pix = (tt * 64 + hy * 4 + sy) * 64 + wx * 4 + sx;
#pragma unroll
  for (int z = 0; z < 3; z++) {
    const float* ga = (z == 0) ? gqg : ((z == 1) ? gkg : gvg);
    const float* be = (z == 0) ? gqb : ((z == 1) ? gkb : gvb);
    float mu = g_mu[z][b][g], rs = g_rs[z][b][g];
    float v = (g_raw[z][b][c][pix] - mu) * rs * ga[c] + be[c];
    if (z == 2) {
      g_vp[b][g][n][e] = v;
    } else {
      float r = v;
      r += __shfl_xor_sync(0xffffffffu, r, 8);
      r += __shfl_xor_sync(0xffffffffu, r, 4);
      r += __shfl_xor_sync(0xffffffffu, r, 2);
      r += __shfl_xor_sync(0xffffffffu, r, 1);
      if (p == 0) {
        if (z == 0) g_qp[b][g][n][d] = r * (1.f / 16.f);
        else        g_kp[b][g][n][d] = r * (1.f / 16.f);
      }
    }
  }
}

// ============================================================
// K4: fused attention v4.
//  - P stored TRANSPOSED: Pt[m][r], stride 68 (float4-aligned; both the
//    8-lane STS.128 store phases and LDS.128 load phases cover all 32
//    banks exactly once -> conflict-free).
//  - Logits: warp owns 8 rows; lane owns m = lane + 32j; j outer, rows
//    inner, exps buffered and written as two STS.128 per j.
//  - PV: warp tile = 32 rows x 16 cols (thread 4x4 outer product),
//    f32x2 packed accumulators.
//  grid (16, 32, 2), 256 threads, ~95.8KB smem, 2 blocks/SM.
// ============================================================
__global__ __launch_bounds__(256, 2) void attn_kernel(
    const float* __restrict__ rel_table, const int* __restrict__ rel_index,
    float* __restrict__ out) {
  extern __shared__ float sm[];
  float* tab = sm;                 // 6728
  float* qs  = tab + 6728;         // 256    [r*4+d]
  float* vs  = qs + 256;           // 8192   [m*64+e]
  float* Pt  = vs + 8192;          // 128*PSTR [m][r] transposed
  float* Sr  = Pt + 128 * PSTR;    // 64 row sums

  const int tile = blockIdx.x, g = blockIdx.y, b = blockIdx.z;
  const int n0 = tile * 64;
  const int t = threadIdx.x;
  const int lane = t & 31, w = t >> 5;

  for (int i = t; i < TBL; i += 256) tab[i] = rel_table[g * TBL + i];
  qs[t] = g_qp[b][g][n0 + (t >> 2)][t & 3];

  ull acc[4][2];
#pragma unroll
  for (int i = 0; i < 4; i++) { acc[i][0] = 0ull; acc[i][1] = 0ull; }
  float srow[8];
#pragma unroll
  for (int k = 0; k < 8; k++) srow[k] = 0.f;

  const int rbase = w * 8;                         // logits rows
  const int rpv = (w & 1) * 32 + (lane & 7) * 4;   // PV rows
  const int cpv = (w >> 1) * 16 + (lane >> 3) * 4; // PV cols

  __syncthreads();

  for (int ch = 0; ch < 8; ch++) {
    const int m0 = ch * 128;
    if (ch) __syncthreads();  // previous PV done before vs/Pt overwrite

    // stage V chunk (128 x 64 floats)
    const float4* vsrc = (const float4*)&g_vp[b][g][m0][0];
#pragma unroll
    for (int i = 0; i < 8; i++)
      ((float4*)vs)[t + i * 256] = vsrc[t + i * 256];

    // logits + exp; j (m-value) outer, rows inner; vector store of 8 exps
#pragma unroll
    for (int j = 0; j < 4; j++) {
      const int m = lane + 32 * j;
      float4 kv = *(const float4*)&g_kp[b][g][m0 + m][0];
      const int* ip = &rel_index[(size_t)(n0 + rbase) * 1024 + m0 + m];
      float e_buf[8];
#pragma unroll
      for (int k = 0; k < 8; k++) {
        float4 qv = *(float4*)&qs[(rbase + k) * 4];
        float l = 0.5f * (qv.x * kv.x + qv.y * kv.y + qv.z * kv.z + qv.w * kv.w)
                  + tab[ip[(size_t)k * 1024]];
        float e = __expf(l);
        e_buf[k] = e;
        srow[k] += e;
      }
      *(float4*)&Pt[m * PSTR + rbase]     = make_float4(e_buf[0], e_buf[1], e_buf[2], e_buf[3]);
      *(float4*)&Pt[m * PSTR + rbase + 4] = make_float4(e_buf[4], e_buf[5], e_buf[6], e_buf[7]);
    }
    __syncthreads();

    // PV: acc[4r][4c] += Pt[m][rpv..+3] (x) vs[m][cpv..+3]
#pragma unroll 4
    for (int m = 0; m < 128; m++) {
      float4 pr = *(float4*)&Pt[m * PSTR + rpv];
      float4 vv = *(float4*)&vs[m * 64 + cpv];
      ull v01 = pack2(vv.x, vv.y), v23 = pack2(vv.z, vv.w);
      ull p0 = pack2(pr.x, pr.x), p1 = pack2(pr.y, pr.y);
      ull p2 = pack2(pr.z, pr.z), p3 = pack2(pr.w, pr.w);
      ffma2(acc[0][0], p0, v01); ffma2(acc[0][1], p0, v23);
      ffma2(acc[1][0], p1, v01); ffma2(acc[1][1], p1, v23);
      ffma2(acc[2][0], p2, v01); ffma2(acc[2][1], p2, v23);
      ffma2(acc[3][0], p3, v01); ffma2(acc[3][1], p3, v23);
    }
  }

  // row sums -> smem (warp w owns rows w*8..w*8+7)
#pragma unroll
  for (int k = 0; k < 8; k++) {
    float s = srow[k];
    s += __shfl_xor_sync(0xffffffffu, s, 16);
    s += __shfl_xor_sync(0xffffffffu, s, 8);
    s += __shfl_xor_sync(0xffffffffu, s, 4);
    s += __shfl_xor_sync(0xffffffffu, s, 2);
    s += __shfl_xor_sync(0xffffffffu, s, 1);
    if (lane == 0) Sr[rbase + k] = s;
  }
  __syncthreads();

  // epilogue: scale by 1/S and scatter to (b,c,t,H,W)
  // col c = cpv + j -> d = w>>1 (head-dim slot), sy = lane>>3, sx = j
  const int d = w >> 1, sy = lane >> 3;
#pragma unroll
  for (int i = 0; i < 4; i++) {
    int r = rpv + i;
    float inv = 1.f / Sr[r];
    float a0, a1, a2, a3;
    unpack2(acc[i][0], a0, a1);
    unpack2(acc[i][1], a2, a3);
    int n = n0 + r;
    int tt = n >> 8, hy = (n >> 4) & 15, wx = n & 15;
    size_t off = ((((size_t)b * 128 + g * 4 + d) * 4 + tt) * 64 + hy * 4 + sy) * 64 + wx * 4;
    *(float4*)&out[off] = make_float4(a0 * inv, a1 * inv, a2 * inv, a3 * inv);
  }
}

// ============================================================
extern "C" void kernel_launch(void* const* d_in, const int* in_sizes, int n_in,
                              void* d_out, int out_size) {
  (void)in_sizes; (void)n_in; (void)out_size;
  const float* x   = (const float*)d_in[0];
  const float* Wq  = (const float*)d_in[1];
  const float* Wk  = (const float*)d_in[2];
  const float* Wv  = (const float*)d_in[3];
  const float* gqg = (const float*)d_in[4];
  const float* gqb = (const float*)d_in[5];
  const float* gkg = (const float*)d_in[6];
  const float* gkb = (const float*)d_in[7];
  const float* gvg = (const float*)d_in[8];
  const float* gvb = (const float*)d_in[9];
  const float* rel_table = (const float*)d_in[10];
  const int*   rel_index = (const int*)d_in[11];
  float* out = (float*)d_out;

  const int smem = (6728 + 256 + 8192 + 128 * PSTR + 64) * sizeof(float);  // 95776
  cudaFuncSetAttribute(attn_kernel, cudaFuncAttributeMaxDynamicSharedMemorySize, smem);

  proj_kernel<<<dim3(256, 2, 3), 256>>>(x, Wq, Wk, Wv);
  gn_stats_kernel<<<192, 256>>>();
  rearrange_kernel<<<16384, 256>>>(gqg, gqb, gkg, gkb, gvg, gvb);
  attn_kernel<<<dim3(16, 32, 2), 256, smem>>>(rel_table, rel_index, out);
}